// round 3
// baseline (speedup 1.0000x reference)
#include <cuda_runtime.h>
#include <cuda_bf16.h>
#include <cstdint>

// Problem constants (fixed by the reference)
#define NN 50000
#define NE 800000
#define F_IN 256
#define F_HID 128
#define F_OUT 64

// ---------------- scratch (__device__ globals; no allocation) ----------------
__device__ float g_h1s[(size_t)NN * F_HID];   // (x@W1)*rs_out, later reused for h1=relu(...)
__device__ float g_agg1[(size_t)NN * F_HID];  // aggregated layer-1 messages
__device__ float g_h2s[(size_t)NN * F_OUT];   // (h1@W2)*rs_out
__device__ float g_agg2[(size_t)NN * F_OUT];  // aggregated layer-2 messages
__device__ int   g_deg_out[NN];
__device__ int   g_deg_in[NN];
__device__ float g_rs_out[NN];
__device__ float g_rs_in[NN];

// ---------------- zero scratch (agg buffers + degree counters) ----------------
__global__ void zero_all_kernel() {
    const int AGG1_V4 = (NN * F_HID) / 4;   // 1,600,000
    const int AGG2_V4 = (NN * F_OUT) / 4;   //   800,000
    const int DEG_V4  = NN / 4;             //    12,500
    int i = blockIdx.x * blockDim.x + threadIdx.x;
    if (i < AGG1_V4) {
        reinterpret_cast<float4*>(g_agg1)[i] = make_float4(0.f, 0.f, 0.f, 0.f);
    } else if (i < AGG1_V4 + AGG2_V4) {
        reinterpret_cast<float4*>(g_agg2)[i - AGG1_V4] = make_float4(0.f, 0.f, 0.f, 0.f);
    } else if (i < AGG1_V4 + AGG2_V4 + DEG_V4) {
        reinterpret_cast<int4*>(g_deg_out)[i - AGG1_V4 - AGG2_V4] = make_int4(0, 0, 0, 0);
    } else if (i < AGG1_V4 + AGG2_V4 + 2 * DEG_V4) {
        reinterpret_cast<int4*>(g_deg_in)[i - AGG1_V4 - AGG2_V4 - DEG_V4] = make_int4(0, 0, 0, 0);
    }
}

// ---------------- degree counting ----------------
__global__ void degree_kernel(const int* __restrict__ src, const int* __restrict__ dst, int E) {
    int i = blockIdx.x * blockDim.x + threadIdx.x;
    if (i >= E) return;
    atomicAdd(&g_deg_out[src[i]], 1);
    atomicAdd(&g_deg_in[dst[i]], 1);
}

__global__ void rsqrt_kernel() {
    int i = blockIdx.x * blockDim.x + threadIdx.x;
    if (i >= NN) return;
    g_rs_out[i] = rsqrtf((float)max(g_deg_out[i], 1));
    g_rs_in[i]  = rsqrtf((float)max(g_deg_in[i], 1));
}

// ---------------- tiled SGEMM with fused row-scale epilogue ----------------
// C[row, :] = (A[row, :] @ B) * rs[row]
// A: [M, K] row-major; B: [K, BN] row-major; single column tile of width BN.
// BM=128, BK=8, TM=8; 256 threads.
template <int BN, int TN>
__device__ __forceinline__ void sgemm_rowscale_core(
    const float* __restrict__ A, const float* __restrict__ B,
    float* __restrict__ C, const float* __restrict__ rs, int M, int K)
{
    constexpr int BM = 128, BK = 8, TM = 8;
    constexpr int TX = BN / TN;  // 16
    __shared__ float As[BK][BM];
    __shared__ float Bs[BK][BN];

    const int tid = threadIdx.x;          // 0..255
    const int tx  = tid % TX;             // 0..15
    const int ty  = tid / TX;             // 0..15
    const int rowBase = blockIdx.x * BM;

    float acc[TM][TN];
#pragma unroll
    for (int i = 0; i < TM; i++)
#pragma unroll
        for (int j = 0; j < TN; j++) acc[i][j] = 0.f;

    // A-tile load mapping: 128 rows x 8 k = 256 float4 (one per thread)
    const int AR = tid >> 1;            // 0..127
    const int AC = (tid & 1) * 4;       // 0 or 4
    // B-tile load mapping
    constexpr int BV = BN / 4;          // float4 per B row
    const int BRow = tid / BV;
    const int BCol = (tid % BV) * 4;

    for (int kt = 0; kt < K; kt += BK) {
        float4 av = make_float4(0.f, 0.f, 0.f, 0.f);
        int ga = rowBase + AR;
        if (ga < M)
            av = *reinterpret_cast<const float4*>(A + (size_t)ga * K + kt + AC);
        As[AC + 0][AR] = av.x;
        As[AC + 1][AR] = av.y;
        As[AC + 2][AR] = av.z;
        As[AC + 3][AR] = av.w;

        if (BRow < BK) {
            float4 bv = *reinterpret_cast<const float4*>(B + (size_t)(kt + BRow) * BN + BCol);
            *reinterpret_cast<float4*>(&Bs[BRow][BCol]) = bv;
        }
        __syncthreads();

#pragma unroll
        for (int kk = 0; kk < BK; kk++) {
            float a[TM], b[TN];
#pragma unroll
            for (int i = 0; i < TM; i++) a[i] = As[kk][ty * TM + i];
#pragma unroll
            for (int j = 0; j < TN; j++) b[j] = Bs[kk][tx * TN + j];
#pragma unroll
            for (int i = 0; i < TM; i++)
#pragma unroll
                for (int j = 0; j < TN; j++) acc[i][j] = fmaf(a[i], b[j], acc[i][j]);
        }
        __syncthreads();
    }

#pragma unroll
    for (int i = 0; i < TM; i++) {
        int row = rowBase + ty * TM + i;
        if (row < M) {
            float s = rs[row];
#pragma unroll
            for (int j = 0; j < TN; j += 4) {
                float4 o = make_float4(acc[i][j] * s, acc[i][j + 1] * s,
                                       acc[i][j + 2] * s, acc[i][j + 3] * s);
                *reinterpret_cast<float4*>(C + (size_t)row * BN + tx * TN + j) = o;
            }
        }
    }
}

// Wrappers bind scratch globals in DEVICE code (host must not pass __device__ symbols).
__global__ __launch_bounds__(256) void gemm1_kernel(const float* __restrict__ x,
                                                    const float* __restrict__ W1) {
    sgemm_rowscale_core<F_HID, 8>(x, W1, g_h1s, g_rs_out, NN, F_IN);
}

__global__ __launch_bounds__(256) void gemm2_kernel(const float* __restrict__ W2) {
    sgemm_rowscale_core<F_OUT, 4>(g_h1s, W2, g_h2s, g_rs_out, NN, F_HID);
}

// ---------------- edge aggregation: one warp per edge ----------------
// agg1[dst] += h1s[src]  (F=128: lane handles 4 consecutive floats, vector red)
__global__ void scatter128_kernel(const int* __restrict__ src, const int* __restrict__ dst, int E) {
    int warp = (blockIdx.x * blockDim.x + threadIdx.x) >> 5;
    int lane = threadIdx.x & 31;
    if (warp >= E) return;
    int s = __ldg(&src[warp]);
    int d = __ldg(&dst[warp]);
    const float4 v = *reinterpret_cast<const float4*>(&g_h1s[(size_t)s * F_HID + lane * 4]);
    float* p = &g_agg1[(size_t)d * F_HID + lane * 4];
    asm volatile("red.global.add.v4.f32 [%0], {%1, %2, %3, %4};"
                 :: "l"(p), "f"(v.x), "f"(v.y), "f"(v.z), "f"(v.w) : "memory");
}

// F=64: lane handles 2 consecutive floats
__global__ void scatter64_kernel(const int* __restrict__ src, const int* __restrict__ dst, int E) {
    int warp = (blockIdx.x * blockDim.x + threadIdx.x) >> 5;
    int lane = threadIdx.x & 31;
    if (warp >= E) return;
    int s = __ldg(&src[warp]);
    int d = __ldg(&dst[warp]);
    const float2 v = *reinterpret_cast<const float2*>(&g_h2s[(size_t)s * F_OUT + lane * 2]);
    float* p = &g_agg2[(size_t)d * F_OUT + lane * 2];
    asm volatile("red.global.add.v2.f32 [%0], {%1, %2};"
                 :: "l"(p), "f"(v.x), "f"(v.y) : "memory");
}

// ---------------- layer-1 epilogue: h1 = relu(agg1 * rs_in + b1) ----------------
__global__ void epi1_kernel(const float* __restrict__ b1) {
    int i = blockIdx.x * blockDim.x + threadIdx.x;  // over NN*32 float4s
    if (i >= NN * (F_HID / 4)) return;
    int row = i >> 5;              // F_HID/4 = 32 float4 per row
    int c4  = (i & 31) * 4;
    float rs = g_rs_in[row];
    float4 v = *reinterpret_cast<const float4*>(&g_agg1[(size_t)row * F_HID + c4]);
    float4 b = *reinterpret_cast<const float4*>(&b1[c4]);
    float4 o;
    o.x = fmaxf(fmaf(v.x, rs, b.x), 0.f);
    o.y = fmaxf(fmaf(v.y, rs, b.y), 0.f);
    o.z = fmaxf(fmaf(v.z, rs, b.z), 0.f);
    o.w = fmaxf(fmaf(v.w, rs, b.w), 0.f);
    *reinterpret_cast<float4*>(&g_h1s[(size_t)row * F_HID + c4]) = o;  // overwrite (safe: scatter done)
}

// ---------------- final: hidden = agg2*rs_in + b2; logits = hidden@Wf + bf ----------------
// One warp per node row.
__global__ void final_kernel(const float* __restrict__ b2, const float* __restrict__ Wf,
                             const float* __restrict__ bf,
                             float* __restrict__ logits, float* __restrict__ hidden) {
    int row  = (blockIdx.x * blockDim.x + threadIdx.x) >> 5;
    int lane = threadIdx.x & 31;
    if (row >= NN) return;
    float rs = g_rs_in[row];
    float2 a = *reinterpret_cast<const float2*>(&g_agg2[(size_t)row * F_OUT + lane * 2]);
    float h0 = fmaf(a.x, rs, b2[lane * 2]);
    float h1 = fmaf(a.y, rs, b2[lane * 2 + 1]);
    *reinterpret_cast<float2*>(&hidden[(size_t)row * F_OUT + lane * 2]) = make_float2(h0, h1);

    // Wf is [64, 2] row-major
    float2 w0 = *reinterpret_cast<const float2*>(&Wf[(lane * 2) * 2]);
    float2 w1 = *reinterpret_cast<const float2*>(&Wf[(lane * 2 + 1) * 2]);
    float p0 = fmaf(h0, w0.x, h1 * w1.x);
    float p1 = fmaf(h0, w0.y, h1 * w1.y);
#pragma unroll
    for (int off = 16; off > 0; off >>= 1) {
        p0 += __shfl_down_sync(0xFFFFFFFFu, p0, off);
        p1 += __shfl_down_sync(0xFFFFFFFFu, p1, off);
    }
    if (lane == 0) {
        logits[(size_t)row * 2 + 0] = p0 + bf[0];
        logits[(size_t)row * 2 + 1] = p1 + bf[1];
    }
}

// ---------------- launcher ----------------
extern "C" void kernel_launch(void* const* d_in, const int* in_sizes, int n_in,
                              void* d_out, int out_size) {
    const float* x   = (const float*)d_in[0];
    const float* W1  = (const float*)d_in[1];
    const float* b1  = (const float*)d_in[2];
    const float* W2  = (const float*)d_in[3];
    const float* b2  = (const float*)d_in[4];
    const float* Wf  = (const float*)d_in[5];
    const float* bf  = (const float*)d_in[6];
    const int*   src = (const int*)d_in[7];
    const int*   dst = (const int*)d_in[8];

    float* out = (float*)d_out;
    float* logits = out;                       // [NN, 2]
    float* hidden = out + (size_t)NN * 2;      // [NN, 64]

    const int E = NE;

    // 1) zero scratch
    {
        const int total = NN * F_HID / 4 + NN * F_OUT / 4 + 2 * (NN / 4);
        zero_all_kernel<<<(total + 255) / 256, 256>>>();
    }
    // 2) degrees + rsqrt norms
    degree_kernel<<<(E + 255) / 256, 256>>>(src, dst, E);
    rsqrt_kernel<<<(NN + 255) / 256, 256>>>();

    // 3) GEMM1 with rs_out row scaling: g_h1s = (x @ W1) * rs_out
    gemm1_kernel<<<(NN + 127) / 128, 256>>>(x, W1);
    // 4) scatter-aggregate (128 features, warp per edge)
    scatter128_kernel<<<(E * 32 + 255) / 256, 256>>>(src, dst, E);
    // 5) h1 = relu(agg1 * rs_in + b1)  (written back into g_h1s)
    epi1_kernel<<<(NN * 32 + 255) / 256, 256>>>(b1);

    // 6) GEMM2 with rs_out row scaling: g_h2s = (h1 @ W2) * rs_out
    gemm2_kernel<<<(NN + 127) / 128, 256>>>(W2);
    // 7) scatter-aggregate (64 features)
    scatter64_kernel<<<(E * 32 + 255) / 256, 256>>>(src, dst, E);
    // 8) hidden + logits
    final_kernel<<<(NN * 32 + 255) / 256, 256>>>(b2, Wf, bf, logits, hidden);
}

// round 4
// speedup vs baseline: 1.3382x; 1.3382x over previous
#include <cuda_runtime.h>
#include <cuda_bf16.h>
#include <cstdint>

// Problem constants (fixed by the reference)
#define NN 50000
#define NE 800000
#define F_IN 256
#define F_HID 128
#define F_OUT 64
#define NBLK_SCAN ((NN + 255) / 256)   // 196

// ---------------- scratch (__device__ globals; no allocation) ----------------
__device__ float g_h1s[(size_t)NN * F_HID];   // (x@W1)*rs_out
__device__ float g_h1 [(size_t)NN * F_HID];   // relu(agg*rs_in + b1)
__device__ float g_h2s[(size_t)NN * F_OUT];   // (h1@W2)*rs_out
__device__ int   g_deg_out[NN];
__device__ int   g_deg_in[NN];
__device__ float g_rs_out[NN];
__device__ float g_rs_in[NN];
__device__ int   g_row_start[NN];
__device__ int   g_cursor[NN];
__device__ int   g_csr[NE];                   // src ids grouped by dst
__device__ int   g_bsum[NBLK_SCAN];
__device__ int   g_boff[NBLK_SCAN];

// ---------------- zero counters ----------------
__global__ void zero_counts_kernel() {
    int i = blockIdx.x * blockDim.x + threadIdx.x;
    if (i < NN) { g_deg_out[i] = 0; g_deg_in[i] = 0; g_cursor[i] = 0; }
}

// ---------------- degree counting ----------------
__global__ void degree_kernel(const int* __restrict__ src, const int* __restrict__ dst) {
    int i = blockIdx.x * blockDim.x + threadIdx.x;
    if (i >= NE) return;
    atomicAdd(&g_deg_out[src[i]], 1);
    atomicAdd(&g_deg_in[dst[i]], 1);
}

__global__ void rsqrt_kernel() {
    int i = blockIdx.x * blockDim.x + threadIdx.x;
    if (i >= NN) return;
    g_rs_out[i] = rsqrtf((float)max(g_deg_out[i], 1));
    g_rs_in[i]  = rsqrtf((float)max(g_deg_in[i], 1));
}

// ---------------- CSR build: block scan of deg_in ----------------
__global__ void scan_a_kernel() {
    __shared__ int s[256];
    int tid = threadIdx.x;
    int i = blockIdx.x * 256 + tid;
    int v = (i < NN) ? g_deg_in[i] : 0;
    s[tid] = v;
    __syncthreads();
#pragma unroll
    for (int off = 1; off < 256; off <<= 1) {
        int t = (tid >= off) ? s[tid - off] : 0;
        __syncthreads();
        s[tid] += t;
        __syncthreads();
    }
    if (i < NN) g_row_start[i] = s[tid] - v;   // exclusive within block
    if (tid == 255) g_bsum[blockIdx.x] = s[255];
}

__global__ void scan_b_kernel() {
    __shared__ int s[256];
    int tid = threadIdx.x;
    int v = (tid < NBLK_SCAN) ? g_bsum[tid] : 0;
    s[tid] = v;
    __syncthreads();
#pragma unroll
    for (int off = 1; off < 256; off <<= 1) {
        int t = (tid >= off) ? s[tid - off] : 0;
        __syncthreads();
        s[tid] += t;
        __syncthreads();
    }
    if (tid < NBLK_SCAN) g_boff[tid] = s[tid] - v;  // exclusive block offsets
}

__global__ void scan_c_kernel() {
    int i = blockIdx.x * blockDim.x + threadIdx.x;
    if (i < NN) g_row_start[i] += g_boff[i >> 8];
}

__global__ void bin_kernel(const int* __restrict__ src, const int* __restrict__ dst) {
    int e = blockIdx.x * blockDim.x + threadIdx.x;
    if (e >= NE) return;
    int d = dst[e];
    int pos = g_row_start[d] + atomicAdd(&g_cursor[d], 1);
    g_csr[pos] = src[e];
}

// ---------------- double-buffered tiled SGEMM with fused row-scale ----------------
// C[row,:] = (A[row,:] @ B) * rs[row];  A [M,K] row-major, B [K,BN] row-major.
// BM=128, BK=16, 256 threads, TM=8 rows x TN cols per thread.
template <int BN, int TN>
__device__ __forceinline__ void sgemm_db_core(
    const float* __restrict__ A, const float* __restrict__ B,
    float* __restrict__ C, const float* __restrict__ rs, int M, int K)
{
    constexpr int BM = 128, BK = 16, TM = 8;
    constexpr int TX = BN / TN;                 // 16
    constexpr int NA = (BM * BK / 4) / 256;     // 2 float4 per thread (A tile)
    constexpr int NB = (BK * BN / 4) / 256;     // 2 (BN=128) or 1 (BN=64)
    constexpr int BNV = BN / 4;                 // float4 per B row

    __shared__ float As[2][BK][BM];
    __shared__ float Bs[2][BK][BN];

    const int tid = threadIdx.x;
    const int tx  = tid % TX;
    const int ty  = tid / TX;
    const int rowBase = blockIdx.x * BM;

    float acc[TM][TN];
#pragma unroll
    for (int i = 0; i < TM; i++)
#pragma unroll
        for (int j = 0; j < TN; j++) acc[i][j] = 0.f;

    float4 aReg[NA], bReg[NB];

    // ---- load tile 0 directly into smem buffer 0 ----
#pragma unroll
    for (int q = 0; q < NA; q++) {
        int f  = tid + q * 256;        // f4 id in [0, 512)
        int m  = f >> 2;
        int kc = (f & 3) * 4;
        float4 av = make_float4(0.f, 0.f, 0.f, 0.f);
        int gr = rowBase + m;
        if (gr < M) av = *reinterpret_cast<const float4*>(A + (size_t)gr * K + kc);
        As[0][kc + 0][m] = av.x;
        As[0][kc + 1][m] = av.y;
        As[0][kc + 2][m] = av.z;
        As[0][kc + 3][m] = av.w;
    }
#pragma unroll
    for (int q = 0; q < NB; q++) {
        int f = tid + q * 256;
        int k = f / BNV;
        int c = (f % BNV) * 4;
        *reinterpret_cast<float4*>(&Bs[0][k][c]) =
            *reinterpret_cast<const float4*>(B + (size_t)k * BN + c);
    }
    __syncthreads();

    const int NT = K / BK;
    for (int kt = 0; kt < NT; kt++) {
        int cur = kt & 1;
        int nxt = cur ^ 1;
        // ---- prefetch next tile into registers ----
        if (kt + 1 < NT) {
            int kbase = (kt + 1) * BK;
#pragma unroll
            for (int q = 0; q < NA; q++) {
                int f  = tid + q * 256;
                int m  = f >> 2;
                int kc = (f & 3) * 4;
                aReg[q] = make_float4(0.f, 0.f, 0.f, 0.f);
                int gr = rowBase + m;
                if (gr < M)
                    aReg[q] = *reinterpret_cast<const float4*>(A + (size_t)gr * K + kbase + kc);
            }
#pragma unroll
            for (int q = 0; q < NB; q++) {
                int f = tid + q * 256;
                int k = f / BNV;
                int c = (f % BNV) * 4;
                bReg[q] = *reinterpret_cast<const float4*>(B + (size_t)(kbase + k) * BN + c);
            }
        }
        // ---- compute on current buffer ----
#pragma unroll
        for (int kk = 0; kk < BK; kk++) {
            float a[TM], b[TN];
            float4 a0 = *reinterpret_cast<const float4*>(&As[cur][kk][ty * TM]);
            float4 a1 = *reinterpret_cast<const float4*>(&As[cur][kk][ty * TM + 4]);
            a[0] = a0.x; a[1] = a0.y; a[2] = a0.z; a[3] = a0.w;
            a[4] = a1.x; a[5] = a1.y; a[6] = a1.z; a[7] = a1.w;
#pragma unroll
            for (int j = 0; j < TN; j += 4) {
                float4 bv = *reinterpret_cast<const float4*>(&Bs[cur][kk][tx * TN + j]);
                b[j] = bv.x; b[j + 1] = bv.y; b[j + 2] = bv.z; b[j + 3] = bv.w;
            }
#pragma unroll
            for (int i = 0; i < TM; i++)
#pragma unroll
                for (int j = 0; j < TN; j++) acc[i][j] = fmaf(a[i], b[j], acc[i][j]);
        }
        // ---- commit prefetched tile ----
        if (kt + 1 < NT) {
#pragma unroll
            for (int q = 0; q < NA; q++) {
                int f  = tid + q * 256;
                int m  = f >> 2;
                int kc = (f & 3) * 4;
                As[nxt][kc + 0][m] = aReg[q].x;
                As[nxt][kc + 1][m] = aReg[q].y;
                As[nxt][kc + 2][m] = aReg[q].z;
                As[nxt][kc + 3][m] = aReg[q].w;
            }
#pragma unroll
            for (int q = 0; q < NB; q++) {
                int f = tid + q * 256;
                int k = f / BNV;
                int c = (f % BNV) * 4;
                *reinterpret_cast<float4*>(&Bs[nxt][k][c]) = bReg[q];
            }
            __syncthreads();
        }
    }

#pragma unroll
    for (int i = 0; i < TM; i++) {
        int row = rowBase + ty * TM + i;
        if (row < M) {
            float s = rs[row];
#pragma unroll
            for (int j = 0; j < TN; j += 4) {
                float4 o = make_float4(acc[i][j] * s, acc[i][j + 1] * s,
                                       acc[i][j + 2] * s, acc[i][j + 3] * s);
                *reinterpret_cast<float4*>(C + (size_t)row * BN + tx * TN + j) = o;
            }
        }
    }
}

__global__ __launch_bounds__(256) void gemm1_kernel(const float* __restrict__ x,
                                                    const float* __restrict__ W1) {
    sgemm_db_core<F_HID, 8>(x, W1, g_h1s, g_rs_out, NN, F_IN);
}

__global__ __launch_bounds__(256) void gemm2_kernel(const float* __restrict__ W2) {
    sgemm_db_core<F_OUT, 4>(g_h1, W2, g_h2s, g_rs_out, NN, F_HID);
}

// ---------------- gather aggregation (CSR, warp per node) ----------------
// g_h1[n,:] = relu( (sum_{s in N_in(n)} g_h1s[s,:]) * rs_in[n] + b1 )
__global__ void gather128_kernel(const float* __restrict__ b1) {
    int node = (blockIdx.x * blockDim.x + threadIdx.x) >> 5;
    int lane = threadIdx.x & 31;
    if (node >= NN) return;
    int start = g_row_start[node];
    int deg   = g_deg_in[node];
    float4 acc = make_float4(0.f, 0.f, 0.f, 0.f);
    for (int base = 0; base < deg; base += 32) {
        int e = base + lane;
        int sid = (e < deg) ? __ldg(&g_csr[start + e]) : 0;
        int cnt = min(32, deg - base);
        int j = 0;
        for (; j + 4 <= cnt; j += 4) {
            int s0 = __shfl_sync(0xFFFFFFFFu, sid, j);
            int s1 = __shfl_sync(0xFFFFFFFFu, sid, j + 1);
            int s2 = __shfl_sync(0xFFFFFFFFu, sid, j + 2);
            int s3 = __shfl_sync(0xFFFFFFFFu, sid, j + 3);
            float4 v0 = __ldg(reinterpret_cast<const float4*>(&g_h1s[(size_t)s0 * F_HID + lane * 4]));
            float4 v1 = __ldg(reinterpret_cast<const float4*>(&g_h1s[(size_t)s1 * F_HID + lane * 4]));
            float4 v2 = __ldg(reinterpret_cast<const float4*>(&g_h1s[(size_t)s2 * F_HID + lane * 4]));
            float4 v3 = __ldg(reinterpret_cast<const float4*>(&g_h1s[(size_t)s3 * F_HID + lane * 4]));
            acc.x += (v0.x + v1.x) + (v2.x + v3.x);
            acc.y += (v0.y + v1.y) + (v2.y + v3.y);
            acc.z += (v0.z + v1.z) + (v2.z + v3.z);
            acc.w += (v0.w + v1.w) + (v2.w + v3.w);
        }
        for (; j < cnt; j++) {
            int s = __shfl_sync(0xFFFFFFFFu, sid, j);
            float4 v = __ldg(reinterpret_cast<const float4*>(&g_h1s[(size_t)s * F_HID + lane * 4]));
            acc.x += v.x; acc.y += v.y; acc.z += v.z; acc.w += v.w;
        }
    }
    float rs = g_rs_in[node];
    float4 b = *reinterpret_cast<const float4*>(&b1[lane * 4]);
    float4 o;
    o.x = fmaxf(fmaf(acc.x, rs, b.x), 0.f);
    o.y = fmaxf(fmaf(acc.y, rs, b.y), 0.f);
    o.z = fmaxf(fmaf(acc.z, rs, b.z), 0.f);
    o.w = fmaxf(fmaf(acc.w, rs, b.w), 0.f);
    *reinterpret_cast<float4*>(&g_h1[(size_t)node * F_HID + lane * 4]) = o;
}

// hidden[n,:] = agg2*rs_in + b2;  logits[n,:] = hidden[n,:] @ Wf + bf
__global__ void gather64_kernel(const float* __restrict__ b2, const float* __restrict__ Wf,
                                const float* __restrict__ bf,
                                float* __restrict__ logits, float* __restrict__ hidden) {
    int node = (blockIdx.x * blockDim.x + threadIdx.x) >> 5;
    int lane = threadIdx.x & 31;
    if (node >= NN) return;
    int start = g_row_start[node];
    int deg   = g_deg_in[node];
    float2 acc = make_float2(0.f, 0.f);
    for (int base = 0; base < deg; base += 32) {
        int e = base + lane;
        int sid = (e < deg) ? __ldg(&g_csr[start + e]) : 0;
        int cnt = min(32, deg - base);
        int j = 0;
        for (; j + 4 <= cnt; j += 4) {
            int s0 = __shfl_sync(0xFFFFFFFFu, sid, j);
            int s1 = __shfl_sync(0xFFFFFFFFu, sid, j + 1);
            int s2 = __shfl_sync(0xFFFFFFFFu, sid, j + 2);
            int s3 = __shfl_sync(0xFFFFFFFFu, sid, j + 3);
            float2 v0 = __ldg(reinterpret_cast<const float2*>(&g_h2s[(size_t)s0 * F_OUT + lane * 2]));
            float2 v1 = __ldg(reinterpret_cast<const float2*>(&g_h2s[(size_t)s1 * F_OUT + lane * 2]));
            float2 v2 = __ldg(reinterpret_cast<const float2*>(&g_h2s[(size_t)s2 * F_OUT + lane * 2]));
            float2 v3 = __ldg(reinterpret_cast<const float2*>(&g_h2s[(size_t)s3 * F_OUT + lane * 2]));
            acc.x += (v0.x + v1.x) + (v2.x + v3.x);
            acc.y += (v0.y + v1.y) + (v2.y + v3.y);
        }
        for (; j < cnt; j++) {
            int s = __shfl_sync(0xFFFFFFFFu, sid, j);
            float2 v = __ldg(reinterpret_cast<const float2*>(&g_h2s[(size_t)s * F_OUT + lane * 2]));
            acc.x += v.x; acc.y += v.y;
        }
    }
    float rs = g_rs_in[node];
    float h0 = fmaf(acc.x, rs, b2[lane * 2]);
    float h1 = fmaf(acc.y, rs, b2[lane * 2 + 1]);
    *reinterpret_cast<float2*>(&hidden[(size_t)node * F_OUT + lane * 2]) = make_float2(h0, h1);

    // Wf [64,2] row-major
    float2 w0 = *reinterpret_cast<const float2*>(&Wf[(lane * 2) * 2]);
    float2 w1 = *reinterpret_cast<const float2*>(&Wf[(lane * 2 + 1) * 2]);
    float p0 = fmaf(h0, w0.x, h1 * w1.x);
    float p1 = fmaf(h0, w0.y, h1 * w1.y);
#pragma unroll
    for (int off = 16; off > 0; off >>= 1) {
        p0 += __shfl_down_sync(0xFFFFFFFFu, p0, off);
        p1 += __shfl_down_sync(0xFFFFFFFFu, p1, off);
    }
    if (lane == 0) {
        logits[(size_t)node * 2 + 0] = p0 + bf[0];
        logits[(size_t)node * 2 + 1] = p1 + bf[1];
    }
}

// ---------------- launcher ----------------
extern "C" void kernel_launch(void* const* d_in, const int* in_sizes, int n_in,
                              void* d_out, int out_size) {
    const float* x   = (const float*)d_in[0];
    const float* W1  = (const float*)d_in[1];
    const float* b1  = (const float*)d_in[2];
    const float* W2  = (const float*)d_in[3];
    const float* b2  = (const float*)d_in[4];
    const float* Wf  = (const float*)d_in[5];
    const float* bf  = (const float*)d_in[6];
    const int*   src = (const int*)d_in[7];
    const int*   dst = (const int*)d_in[8];

    float* out = (float*)d_out;
    float* logits = out;                       // [NN, 2]
    float* hidden = out + (size_t)NN * 2;      // [NN, 64]

    zero_counts_kernel<<<(NN + 255) / 256, 256>>>();
    degree_kernel<<<(NE + 255) / 256, 256>>>(src, dst);
    rsqrt_kernel<<<(NN + 255) / 256, 256>>>();

    // CSR build (grouped by dst)
    scan_a_kernel<<<NBLK_SCAN, 256>>>();
    scan_b_kernel<<<1, 256>>>();
    scan_c_kernel<<<NBLK_SCAN, 256>>>();
    bin_kernel<<<(NE + 255) / 256, 256>>>(src, dst);

    // Layer 1
    gemm1_kernel<<<(NN + 127) / 128, 256>>>(x, W1);
    gather128_kernel<<<(NN * 32 + 255) / 256, 256>>>(b1);

    // Layer 2 + head
    gemm2_kernel<<<(NN + 127) / 128, 256>>>(W2);
    gather64_kernel<<<(NN * 32 + 255) / 256, 256>>>(b2, Wf, bf, logits, hidden);
}

// round 5
// speedup vs baseline: 1.7080x; 1.2764x over previous
#include <cuda_runtime.h>
#include <cuda_bf16.h>
#include <cstdint>

// Problem constants (fixed by the reference)
#define NN 50000
#define NE 800000
#define F_IN 256
#define F_HID 128
#define F_OUT 64
#define NBLK_SCAN ((NN + 255) / 256)   // 196

// ---------------- scratch (__device__ globals; no allocation) ----------------
__device__ float g_h1s[(size_t)NN * F_HID];   // (x@W1)*rs_out
__device__ float g_h1 [(size_t)NN * F_HID];   // relu(agg*rs_in + b1)
__device__ float g_h2s[(size_t)NN * F_OUT];   // (h1@W2)*rs_out
__device__ int   g_deg_out[NN];
__device__ int   g_deg_in[NN];
__device__ float g_rs_out[NN];
__device__ float g_rs_in[NN];
__device__ int   g_row_start[NN];
__device__ int   g_cursor[NN];
__device__ int   g_csr[NE];                   // src ids grouped by dst
__device__ int   g_bsum[NBLK_SCAN];
__device__ int   g_boff[NBLK_SCAN];

// ---------------- zero counters ----------------
__global__ void zero_counts_kernel() {
    int i = blockIdx.x * blockDim.x + threadIdx.x;
    if (i < NN) { g_deg_out[i] = 0; g_deg_in[i] = 0; g_cursor[i] = 0; }
}

// ---------------- degree counting ----------------
__global__ void degree_kernel(const int* __restrict__ src, const int* __restrict__ dst) {
    int i = blockIdx.x * blockDim.x + threadIdx.x;
    if (i >= NE) return;
    atomicAdd(&g_deg_out[src[i]], 1);
    atomicAdd(&g_deg_in[dst[i]], 1);
}

__global__ void rsqrt_kernel() {
    int i = blockIdx.x * blockDim.x + threadIdx.x;
    if (i >= NN) return;
    g_rs_out[i] = rsqrtf((float)max(g_deg_out[i], 1));
    g_rs_in[i]  = rsqrtf((float)max(g_deg_in[i], 1));
}

// ---------------- CSR build: block scan of deg_in ----------------
__global__ void scan_a_kernel() {
    __shared__ int s[256];
    int tid = threadIdx.x;
    int i = blockIdx.x * 256 + tid;
    int v = (i < NN) ? g_deg_in[i] : 0;
    s[tid] = v;
    __syncthreads();
#pragma unroll
    for (int off = 1; off < 256; off <<= 1) {
        int t = (tid >= off) ? s[tid - off] : 0;
        __syncthreads();
        s[tid] += t;
        __syncthreads();
    }
    if (i < NN) g_row_start[i] = s[tid] - v;
    if (tid == 255) g_bsum[blockIdx.x] = s[255];
}

__global__ void scan_b_kernel() {
    __shared__ int s[256];
    int tid = threadIdx.x;
    int v = (tid < NBLK_SCAN) ? g_bsum[tid] : 0;
    s[tid] = v;
    __syncthreads();
#pragma unroll
    for (int off = 1; off < 256; off <<= 1) {
        int t = (tid >= off) ? s[tid - off] : 0;
        __syncthreads();
        s[tid] += t;
        __syncthreads();
    }
    if (tid < NBLK_SCAN) g_boff[tid] = s[tid] - v;
}

__global__ void scan_c_kernel() {
    int i = blockIdx.x * blockDim.x + threadIdx.x;
    if (i < NN) g_row_start[i] += g_boff[i >> 8];
}

__global__ void bin_kernel(const int* __restrict__ src, const int* __restrict__ dst) {
    int e = blockIdx.x * blockDim.x + threadIdx.x;
    if (e >= NE) return;
    int d = dst[e];
    int pos = g_row_start[d] + atomicAdd(&g_cursor[d], 1);
    g_csr[pos] = src[e];
}

// ---------------- tf32 tensor-core helpers ----------------
__device__ __forceinline__ uint32_t f2tf32(float f) {
    uint32_t u;
    asm("cvt.rna.tf32.f32 %0, %1;" : "=r"(u) : "f"(f));
    return u;
}

__device__ __forceinline__ void mma_tf32(float* d, const uint32_t* a, const uint32_t* b) {
    asm volatile(
        "mma.sync.aligned.m16n8k8.row.col.f32.tf32.tf32.f32 "
        "{%0,%1,%2,%3}, {%4,%5,%6,%7}, {%8,%9}, {%0,%1,%2,%3};"
        : "+f"(d[0]), "+f"(d[1]), "+f"(d[2]), "+f"(d[3])
        : "r"(a[0]), "r"(a[1]), "r"(a[2]), "r"(a[3]), "r"(b[0]), "r"(b[1]));
}

// ---------------- 3xTF32 tensor GEMM with fused row-scale ----------------
// C[row,:] = (A[row,:] @ B) * rs[row];  A [M,K] row-major, B [K,BN] row-major.
// BM=128, BK=16, 256 threads = 8 warps arranged WM x WN.
// Warp tile: (BM/WM) x (BN/WN); each warp MT x NT m16n8k8 tiles per k8-step.
template <int BN, int WM, int WN>
__device__ __forceinline__ void mma_gemm_core(
    const float* __restrict__ A, const float* __restrict__ B,
    float* __restrict__ C, const float* __restrict__ rs, int M, int K)
{
    constexpr int BM = 128, BK = 16;
    constexpr int WTM = BM / WM;
    constexpr int WTN = BN / WN;
    constexpr int MT = WTM / 16;
    constexpr int NT = WTN / 8;
    constexpr int NA = (BM * BK / 4) / 256;     // float4 per thread for A tile (=2)
    constexpr int NB = (BK * BN / 4) / 256;     // 2 (BN=128) or 1 (BN=64)
    constexpr int BNV = BN / 4;
    constexpr int PAD = 8;

    __shared__ float As[2][BK][BM + PAD];
    __shared__ float Bs[2][BK][BN + PAD];

    const int tid  = threadIdx.x;
    const int w    = tid >> 5;
    const int lane = tid & 31;
    const int g    = lane >> 2;     // groupID
    const int tig  = lane & 3;      // threadID_in_group
    const int wm   = w % WM;
    const int wn   = w / WM;
    const int rowBase = blockIdx.x * BM;

    float acc[MT][NT][4];
#pragma unroll
    for (int i = 0; i < MT; i++)
#pragma unroll
        for (int j = 0; j < NT; j++)
#pragma unroll
            for (int q = 0; q < 4; q++) acc[i][j][q] = 0.f;

    float4 aReg[NA], bReg[NB];

    // ---- load tile 0 into buffer 0 ----
#pragma unroll
    for (int q = 0; q < NA; q++) {
        int f  = tid + q * 256;        // float4 id in [0, 512)
        int m  = f >> 2;
        int kc = (f & 3) * 4;
        float4 av = make_float4(0.f, 0.f, 0.f, 0.f);
        int gr = rowBase + m;
        if (gr < M) av = *reinterpret_cast<const float4*>(A + (size_t)gr * K + kc);
        As[0][kc + 0][m] = av.x;
        As[0][kc + 1][m] = av.y;
        As[0][kc + 2][m] = av.z;
        As[0][kc + 3][m] = av.w;
    }
#pragma unroll
    for (int q = 0; q < NB; q++) {
        int f = tid + q * 256;
        int k = f / BNV;
        int c = (f % BNV) * 4;
        float4 bv = *reinterpret_cast<const float4*>(B + (size_t)k * BN + c);
        Bs[0][k][c + 0] = bv.x;
        Bs[0][k][c + 1] = bv.y;
        Bs[0][k][c + 2] = bv.z;
        Bs[0][k][c + 3] = bv.w;
    }
    __syncthreads();

    const int NTILES = K / BK;
    for (int kt = 0; kt < NTILES; kt++) {
        int cur = kt & 1;
        int nxt = cur ^ 1;
        // ---- prefetch next tile into registers ----
        if (kt + 1 < NTILES) {
            int kbase = (kt + 1) * BK;
#pragma unroll
            for (int q = 0; q < NA; q++) {
                int f  = tid + q * 256;
                int m  = f >> 2;
                int kc = (f & 3) * 4;
                aReg[q] = make_float4(0.f, 0.f, 0.f, 0.f);
                int gr = rowBase + m;
                if (gr < M)
                    aReg[q] = *reinterpret_cast<const float4*>(A + (size_t)gr * K + kbase + kc);
            }
#pragma unroll
            for (int q = 0; q < NB; q++) {
                int f = tid + q * 256;
                int k = f / BNV;
                int c = (f % BNV) * 4;
                bReg[q] = *reinterpret_cast<const float4*>(B + (size_t)(kbase + k) * BN + c);
            }
        }
        // ---- compute on current buffer: two k8-steps ----
#pragma unroll
        for (int kk = 0; kk < BK; kk += 8) {
            // B fragments (hi/lo) for all NT tiles
            uint32_t bh[NT][2], bl[NT][2];
#pragma unroll
            for (int ni = 0; ni < NT; ni++) {
                int bc = wn * WTN + ni * 8 + g;
                float b0 = Bs[cur][kk + tig][bc];
                float b1 = Bs[cur][kk + tig + 4][bc];
                bh[ni][0] = f2tf32(b0);
                bl[ni][0] = f2tf32(b0 - __uint_as_float(bh[ni][0]));
                bh[ni][1] = f2tf32(b1);
                bl[ni][1] = f2tf32(b1 - __uint_as_float(bh[ni][1]));
            }
#pragma unroll
            for (int mi = 0; mi < MT; mi++) {
                int ar = wm * WTM + mi * 16 + g;
                float a0 = As[cur][kk + tig][ar];
                float a1 = As[cur][kk + tig][ar + 8];
                float a2 = As[cur][kk + tig + 4][ar];
                float a3 = As[cur][kk + tig + 4][ar + 8];
                uint32_t ah[4], al[4];
                ah[0] = f2tf32(a0); al[0] = f2tf32(a0 - __uint_as_float(ah[0]));
                ah[1] = f2tf32(a1); al[1] = f2tf32(a1 - __uint_as_float(ah[1]));
                ah[2] = f2tf32(a2); al[2] = f2tf32(a2 - __uint_as_float(ah[2]));
                ah[3] = f2tf32(a3); al[3] = f2tf32(a3 - __uint_as_float(ah[3]));
#pragma unroll
                for (int ni = 0; ni < NT; ni++) {
                    mma_tf32(acc[mi][ni], ah, bh[ni]);   // hi*hi
                    mma_tf32(acc[mi][ni], al, bh[ni]);   // lo*hi
                    mma_tf32(acc[mi][ni], ah, bl[ni]);   // hi*lo
                }
            }
        }
        // ---- commit prefetched tile ----
        if (kt + 1 < NTILES) {
            __syncthreads();
#pragma unroll
            for (int q = 0; q < NA; q++) {
                int f  = tid + q * 256;
                int m  = f >> 2;
                int kc = (f & 3) * 4;
                As[nxt][kc + 0][m] = aReg[q].x;
                As[nxt][kc + 1][m] = aReg[q].y;
                As[nxt][kc + 2][m] = aReg[q].z;
                As[nxt][kc + 3][m] = aReg[q].w;
            }
#pragma unroll
            for (int q = 0; q < NB; q++) {
                int f = tid + q * 256;
                int k = f / BNV;
                int c = (f % BNV) * 4;
                Bs[nxt][k][c + 0] = bReg[q].x;
                Bs[nxt][k][c + 1] = bReg[q].y;
                Bs[nxt][k][c + 2] = bReg[q].z;
                Bs[nxt][k][c + 3] = bReg[q].w;
            }
            __syncthreads();
        }
    }

    // ---- epilogue: row-scale and store ----
#pragma unroll
    for (int mi = 0; mi < MT; mi++) {
        int r0 = rowBase + wm * WTM + mi * 16 + g;
        int r1 = r0 + 8;
        float s0 = (r0 < M) ? rs[r0] : 0.f;
        float s1 = (r1 < M) ? rs[r1] : 0.f;
#pragma unroll
        for (int ni = 0; ni < NT; ni++) {
            int c = wn * WTN + ni * 8 + tig * 2;
            if (r0 < M) {
                float2 o = make_float2(acc[mi][ni][0] * s0, acc[mi][ni][1] * s0);
                *reinterpret_cast<float2*>(C + (size_t)r0 * BN + c) = o;
            }
            if (r1 < M) {
                float2 o = make_float2(acc[mi][ni][2] * s1, acc[mi][ni][3] * s1);
                *reinterpret_cast<float2*>(C + (size_t)r1 * BN + c) = o;
            }
        }
    }
}

__global__ __launch_bounds__(256) void gemm1_kernel(const float* __restrict__ x,
                                                    const float* __restrict__ W1) {
    mma_gemm_core<F_HID, 2, 4>(x, W1, g_h1s, g_rs_out, NN, F_IN);
}

__global__ __launch_bounds__(256) void gemm2_kernel(const float* __restrict__ W2) {
    mma_gemm_core<F_OUT, 4, 2>(g_h1, W2, g_h2s, g_rs_out, NN, F_HID);
}

// ---------------- gather aggregation (CSR, warp per node) ----------------
__global__ void gather128_kernel(const float* __restrict__ b1) {
    int node = (blockIdx.x * blockDim.x + threadIdx.x) >> 5;
    int lane = threadIdx.x & 31;
    if (node >= NN) return;
    int start = g_row_start[node];
    int deg   = g_deg_in[node];
    float4 acc = make_float4(0.f, 0.f, 0.f, 0.f);
    for (int base = 0; base < deg; base += 32) {
        int e = base + lane;
        int sid = (e < deg) ? __ldg(&g_csr[start + e]) : 0;
        int cnt = min(32, deg - base);
        int j = 0;
        for (; j + 4 <= cnt; j += 4) {
            int s0 = __shfl_sync(0xFFFFFFFFu, sid, j);
            int s1 = __shfl_sync(0xFFFFFFFFu, sid, j + 1);
            int s2 = __shfl_sync(0xFFFFFFFFu, sid, j + 2);
            int s3 = __shfl_sync(0xFFFFFFFFu, sid, j + 3);
            float4 v0 = __ldg(reinterpret_cast<const float4*>(&g_h1s[(size_t)s0 * F_HID + lane * 4]));
            float4 v1 = __ldg(reinterpret_cast<const float4*>(&g_h1s[(size_t)s1 * F_HID + lane * 4]));
            float4 v2 = __ldg(reinterpret_cast<const float4*>(&g_h1s[(size_t)s2 * F_HID + lane * 4]));
            float4 v3 = __ldg(reinterpret_cast<const float4*>(&g_h1s[(size_t)s3 * F_HID + lane * 4]));
            acc.x += (v0.x + v1.x) + (v2.x + v3.x);
            acc.y += (v0.y + v1.y) + (v2.y + v3.y);
            acc.z += (v0.z + v1.z) + (v2.z + v3.z);
            acc.w += (v0.w + v1.w) + (v2.w + v3.w);
        }
        for (; j < cnt; j++) {
            int s = __shfl_sync(0xFFFFFFFFu, sid, j);
            float4 v = __ldg(reinterpret_cast<const float4*>(&g_h1s[(size_t)s * F_HID + lane * 4]));
            acc.x += v.x; acc.y += v.y; acc.z += v.z; acc.w += v.w;
        }
    }
    float rs = g_rs_in[node];
    float4 b = *reinterpret_cast<const float4*>(&b1[lane * 4]);
    float4 o;
    o.x = fmaxf(fmaf(acc.x, rs, b.x), 0.f);
    o.y = fmaxf(fmaf(acc.y, rs, b.y), 0.f);
    o.z = fmaxf(fmaf(acc.z, rs, b.z), 0.f);
    o.w = fmaxf(fmaf(acc.w, rs, b.w), 0.f);
    *reinterpret_cast<float4*>(&g_h1[(size_t)node * F_HID + lane * 4]) = o;
}

__global__ void gather64_kernel(const float* __restrict__ b2, const float* __restrict__ Wf,
                                const float* __restrict__ bf,
                                float* __restrict__ logits, float* __restrict__ hidden) {
    int node = (blockIdx.x * blockDim.x + threadIdx.x) >> 5;
    int lane = threadIdx.x & 31;
    if (node >= NN) return;
    int start = g_row_start[node];
    int deg   = g_deg_in[node];
    float2 acc = make_float2(0.f, 0.f);
    for (int base = 0; base < deg; base += 32) {
        int e = base + lane;
        int sid = (e < deg) ? __ldg(&g_csr[start + e]) : 0;
        int cnt = min(32, deg - base);
        int j = 0;
        for (; j + 4 <= cnt; j += 4) {
            int s0 = __shfl_sync(0xFFFFFFFFu, sid, j);
            int s1 = __shfl_sync(0xFFFFFFFFu, sid, j + 1);
            int s2 = __shfl_sync(0xFFFFFFFFu, sid, j + 2);
            int s3 = __shfl_sync(0xFFFFFFFFu, sid, j + 3);
            float2 v0 = __ldg(reinterpret_cast<const float2*>(&g_h2s[(size_t)s0 * F_OUT + lane * 2]));
            float2 v1 = __ldg(reinterpret_cast<const float2*>(&g_h2s[(size_t)s1 * F_OUT + lane * 2]));
            float2 v2 = __ldg(reinterpret_cast<const float2*>(&g_h2s[(size_t)s2 * F_OUT + lane * 2]));
            float2 v3 = __ldg(reinterpret_cast<const float2*>(&g_h2s[(size_t)s3 * F_OUT + lane * 2]));
            acc.x += (v0.x + v1.x) + (v2.x + v3.x);
            acc.y += (v0.y + v1.y) + (v2.y + v3.y);
        }
        for (; j < cnt; j++) {
            int s = __shfl_sync(0xFFFFFFFFu, sid, j);
            float2 v = __ldg(reinterpret_cast<const float2*>(&g_h2s[(size_t)s * F_OUT + lane * 2]));
            acc.x += v.x; acc.y += v.y;
        }
    }
    float rs = g_rs_in[node];
    float h0 = fmaf(acc.x, rs, b2[lane * 2]);
    float h1 = fmaf(acc.y, rs, b2[lane * 2 + 1]);
    *reinterpret_cast<float2*>(&hidden[(size_t)node * F_OUT + lane * 2]) = make_float2(h0, h1);

    float2 w0 = *reinterpret_cast<const float2*>(&Wf[(lane * 2) * 2]);
    float2 w1 = *reinterpret_cast<const float2*>(&Wf[(lane * 2 + 1) * 2]);
    float p0 = fmaf(h0, w0.x, h1 * w1.x);
    float p1 = fmaf(h0, w0.y, h1 * w1.y);
#pragma unroll
    for (int off = 16; off > 0; off >>= 1) {
        p0 += __shfl_down_sync(0xFFFFFFFFu, p0, off);
        p1 += __shfl_down_sync(0xFFFFFFFFu, p1, off);
    }
    if (lane == 0) {
        logits[(size_t)node * 2 + 0] = p0 + bf[0];
        logits[(size_t)node * 2 + 1] = p1 + bf[1];
    }
}

// ---------------- launcher ----------------
extern "C" void kernel_launch(void* const* d_in, const int* in_sizes, int n_in,
                              void* d_out, int out_size) {
    const float* x   = (const float*)d_in[0];
    const float* W1  = (const float*)d_in[1];
    const float* b1  = (const float*)d_in[2];
    const float* W2  = (const float*)d_in[3];
    const float* b2  = (const float*)d_in[4];
    const float* Wf  = (const float*)d_in[5];
    const float* bf  = (const float*)d_in[6];
    const int*   src = (const int*)d_in[7];
    const int*   dst = (const int*)d_in[8];

    float* out = (float*)d_out;
    float* logits = out;                       // [NN, 2]
    float* hidden = out + (size_t)NN * 2;      // [NN, 64]

    zero_counts_kernel<<<(NN + 255) / 256, 256>>>();
    degree_kernel<<<(NE + 255) / 256, 256>>>(src, dst);
    rsqrt_kernel<<<(NN + 255) / 256, 256>>>();

    // CSR build (grouped by dst)
    scan_a_kernel<<<NBLK_SCAN, 256>>>();
    scan_b_kernel<<<1, 256>>>();
    scan_c_kernel<<<NBLK_SCAN, 256>>>();
    bin_kernel<<<(NE + 255) / 256, 256>>>(src, dst);

    // Layer 1
    gemm1_kernel<<<(NN + 127) / 128, 256>>>(x, W1);
    gather128_kernel<<<(NN * 32 + 255) / 256, 256>>>(b1);

    // Layer 2 + head
    gemm2_kernel<<<(NN + 127) / 128, 256>>>(W2);
    gather64_kernel<<<(NN * 32 + 255) / 256, 256>>>(b2, Wf, bf, logits, hidden);
}

// round 6
// speedup vs baseline: 1.8449x; 1.0801x over previous
#include <cuda_runtime.h>
#include <cuda_bf16.h>
#include <cstdint>

// Problem constants (fixed by the reference)
#define NN 50000
#define NE 800000
#define F_IN 256
#define F_HID 128
#define F_OUT 64
#define NBLK_SCAN ((NN + 255) / 256)   // 196

// ---------------- scratch (__device__ globals; no allocation) ----------------
__device__ float g_h1s[(size_t)NN * F_HID];   // (x@W1)*rs_out
__device__ float g_h1 [(size_t)NN * F_HID];   // relu(agg*rs_in + b1)
__device__ float g_h2s[(size_t)NN * F_OUT];   // (h1@W2)*rs_out
__device__ int   g_deg_out[NN];
__device__ int   g_deg_in[NN];
__device__ float g_rs_out[NN];
__device__ float g_rs_in[NN];
__device__ int   g_row_start[NN];
__device__ int   g_cursor[NN];
__device__ int   g_csr[NE];                   // src ids grouped by dst
__device__ int   g_bsum[NBLK_SCAN];
__device__ int   g_boff[NBLK_SCAN];

// ---------------- streams/events for fork-join (created once at load) ----------------
struct ForkJoin {
    cudaStream_t s2;
    cudaEvent_t  evFork, evJoin;
    ForkJoin() {
        cudaStreamCreateWithFlags(&s2, cudaStreamNonBlocking);
        cudaEventCreateWithFlags(&evFork, cudaEventDisableTiming);
        cudaEventCreateWithFlags(&evJoin, cudaEventDisableTiming);
    }
};
static ForkJoin g_fj;

// ---------------- zero counters ----------------
__global__ void zero_counts_kernel() {
    int i = blockIdx.x * blockDim.x + threadIdx.x;
    if (i < NN) { g_deg_out[i] = 0; g_deg_in[i] = 0; g_cursor[i] = 0; }
}

// ---------------- degree counting ----------------
__global__ void degree_kernel(const int* __restrict__ src, const int* __restrict__ dst) {
    int i = blockIdx.x * blockDim.x + threadIdx.x;
    if (i >= NE) return;
    atomicAdd(&g_deg_out[__ldg(&src[i])], 1);
    atomicAdd(&g_deg_in[__ldg(&dst[i])], 1);
}

__global__ void rsqrt_kernel() {
    int i = blockIdx.x * blockDim.x + threadIdx.x;
    if (i >= NN) return;
    g_rs_out[i] = rsqrtf((float)max(g_deg_out[i], 1));
    g_rs_in[i]  = rsqrtf((float)max(g_deg_in[i], 1));
}

// ---------------- CSR build: block scan of deg_in ----------------
__global__ void scan_a_kernel() {
    __shared__ int s[256];
    int tid = threadIdx.x;
    int i = blockIdx.x * 256 + tid;
    int v = (i < NN) ? g_deg_in[i] : 0;
    s[tid] = v;
    __syncthreads();
#pragma unroll
    for (int off = 1; off < 256; off <<= 1) {
        int t = (tid >= off) ? s[tid - off] : 0;
        __syncthreads();
        s[tid] += t;
        __syncthreads();
    }
    if (i < NN) g_row_start[i] = s[tid] - v;
    if (tid == 255) g_bsum[blockIdx.x] = s[255];
}

__global__ void scan_b_kernel() {
    __shared__ int s[256];
    int tid = threadIdx.x;
    int v = (tid < NBLK_SCAN) ? g_bsum[tid] : 0;
    s[tid] = v;
    __syncthreads();
#pragma unroll
    for (int off = 1; off < 256; off <<= 1) {
        int t = (tid >= off) ? s[tid - off] : 0;
        __syncthreads();
        s[tid] += t;
        __syncthreads();
    }
    if (tid < NBLK_SCAN) g_boff[tid] = s[tid] - v;
}

__global__ void scan_c_kernel() {
    int i = blockIdx.x * blockDim.x + threadIdx.x;
    if (i < NN) g_row_start[i] += g_boff[i >> 8];
}

__global__ void bin_kernel(const int* __restrict__ src, const int* __restrict__ dst) {
    int e = blockIdx.x * blockDim.x + threadIdx.x;
    if (e >= NE) return;
    int d = __ldg(&dst[e]);
    int pos = g_row_start[d] + atomicAdd(&g_cursor[d], 1);
    g_csr[pos] = __ldg(&src[e]);
}

// ---------------- tf32 tensor-core helpers ----------------
__device__ __forceinline__ uint32_t f2tf32(float f) {
    uint32_t u;
    asm("cvt.rna.tf32.f32 %0, %1;" : "=r"(u) : "f"(f));
    return u;
}

__device__ __forceinline__ void mma_tf32(float* d, const uint32_t* a, const uint32_t* b) {
    asm volatile(
        "mma.sync.aligned.m16n8k8.row.col.f32.tf32.tf32.f32 "
        "{%0,%1,%2,%3}, {%4,%5,%6,%7}, {%8,%9}, {%0,%1,%2,%3};"
        : "+f"(d[0]), "+f"(d[1]), "+f"(d[2]), "+f"(d[3])
        : "r"(a[0]), "r"(a[1]), "r"(a[2]), "r"(a[3]), "r"(b[0]), "r"(b[1]));
}

// ---------------- 3xTF32 tensor GEMM with fused row-scale ----------------
// C[row,:] = (A[row,:] @ B) * rs[row];  A [M,K] row-major, B [K,BN] row-major.
// BM=128, BK=16, 256 threads = 8 warps arranged WM x WN.
template <int BN, int WM, int WN>
__device__ __forceinline__ void mma_gemm_core(
    const float* __restrict__ A, const float* __restrict__ B,
    float* __restrict__ C, const float* __restrict__ rs, int M, int K)
{
    constexpr int BM = 128, BK = 16;
    constexpr int WTM = BM / WM;
    constexpr int WTN = BN / WN;
    constexpr int MT = WTM / 16;
    constexpr int NT = WTN / 8;
    constexpr int NA = (BM * BK / 4) / 256;     // =2
    constexpr int NB = (BK * BN / 4) / 256;     // 2 (BN=128) or 1 (BN=64)
    constexpr int BNV = BN / 4;
    constexpr int PAD = 8;

    __shared__ float As[2][BK][BM + PAD];
    __shared__ float Bs[2][BK][BN + PAD];

    const int tid  = threadIdx.x;
    const int w    = tid >> 5;
    const int lane = tid & 31;
    const int g    = lane >> 2;
    const int tig  = lane & 3;
    const int wm   = w % WM;
    const int wn   = w / WM;
    const int rowBase = blockIdx.x * BM;

    float acc[MT][NT][4];
#pragma unroll
    for (int i = 0; i < MT; i++)
#pragma unroll
        for (int j = 0; j < NT; j++)
#pragma unroll
            for (int q = 0; q < 4; q++) acc[i][j][q] = 0.f;

    float4 aReg[NA], bReg[NB];

    // ---- load tile 0 into buffer 0 ----
#pragma unroll
    for (int q = 0; q < NA; q++) {
        int f  = tid + q * 256;
        int m  = f >> 2;
        int kc = (f & 3) * 4;
        float4 av = make_float4(0.f, 0.f, 0.f, 0.f);
        int gr = rowBase + m;
        if (gr < M) av = *reinterpret_cast<const float4*>(A + (size_t)gr * K + kc);
        As[0][kc + 0][m] = av.x;
        As[0][kc + 1][m] = av.y;
        As[0][kc + 2][m] = av.z;
        As[0][kc + 3][m] = av.w;
    }
#pragma unroll
    for (int q = 0; q < NB; q++) {
        int f = tid + q * 256;
        int k = f / BNV;
        int c = (f % BNV) * 4;
        float4 bv = *reinterpret_cast<const float4*>(B + (size_t)k * BN + c);
        Bs[0][k][c + 0] = bv.x;
        Bs[0][k][c + 1] = bv.y;
        Bs[0][k][c + 2] = bv.z;
        Bs[0][k][c + 3] = bv.w;
    }
    __syncthreads();

    const int NTILES = K / BK;
    for (int kt = 0; kt < NTILES; kt++) {
        int cur = kt & 1;
        int nxt = cur ^ 1;
        if (kt + 1 < NTILES) {
            int kbase = (kt + 1) * BK;
#pragma unroll
            for (int q = 0; q < NA; q++) {
                int f  = tid + q * 256;
                int m  = f >> 2;
                int kc = (f & 3) * 4;
                aReg[q] = make_float4(0.f, 0.f, 0.f, 0.f);
                int gr = rowBase + m;
                if (gr < M)
                    aReg[q] = *reinterpret_cast<const float4*>(A + (size_t)gr * K + kbase + kc);
            }
#pragma unroll
            for (int q = 0; q < NB; q++) {
                int f = tid + q * 256;
                int k = f / BNV;
                int c = (f % BNV) * 4;
                bReg[q] = *reinterpret_cast<const float4*>(B + (size_t)(kbase + k) * BN + c);
            }
        }
#pragma unroll
        for (int kk = 0; kk < BK; kk += 8) {
            uint32_t bh[NT][2], bl[NT][2];
#pragma unroll
            for (int ni = 0; ni < NT; ni++) {
                int bc = wn * WTN + ni * 8 + g;
                float b0 = Bs[cur][kk + tig][bc];
                float b1 = Bs[cur][kk + tig + 4][bc];
                bh[ni][0] = f2tf32(b0);
                bl[ni][0] = f2tf32(b0 - __uint_as_float(bh[ni][0]));
                bh[ni][1] = f2tf32(b1);
                bl[ni][1] = f2tf32(b1 - __uint_as_float(bh[ni][1]));
            }
#pragma unroll
            for (int mi = 0; mi < MT; mi++) {
                int ar = wm * WTM + mi * 16 + g;
                float a0 = As[cur][kk + tig][ar];
                float a1 = As[cur][kk + tig][ar + 8];
                float a2 = As[cur][kk + tig + 4][ar];
                float a3 = As[cur][kk + tig + 4][ar + 8];
                uint32_t ah[4], al[4];
                ah[0] = f2tf32(a0); al[0] = f2tf32(a0 - __uint_as_float(ah[0]));
                ah[1] = f2tf32(a1); al[1] = f2tf32(a1 - __uint_as_float(ah[1]));
                ah[2] = f2tf32(a2); al[2] = f2tf32(a2 - __uint_as_float(ah[2]));
                ah[3] = f2tf32(a3); al[3] = f2tf32(a3 - __uint_as_float(ah[3]));
#pragma unroll
                for (int ni = 0; ni < NT; ni++) {
                    mma_tf32(acc[mi][ni], ah, bh[ni]);
                    mma_tf32(acc[mi][ni], al, bh[ni]);
                    mma_tf32(acc[mi][ni], ah, bl[ni]);
                }
            }
        }
        if (kt + 1 < NTILES) {
            __syncthreads();
#pragma unroll
            for (int q = 0; q < NA; q++) {
                int f  = tid + q * 256;
                int m  = f >> 2;
                int kc = (f & 3) * 4;
                As[nxt][kc + 0][m] = aReg[q].x;
                As[nxt][kc + 1][m] = aReg[q].y;
                As[nxt][kc + 2][m] = aReg[q].z;
                As[nxt][kc + 3][m] = aReg[q].w;
            }
#pragma unroll
            for (int q = 0; q < NB; q++) {
                int f = tid + q * 256;
                int k = f / BNV;
                int c = (f % BNV) * 4;
                Bs[nxt][k][c + 0] = bReg[q].x;
                Bs[nxt][k][c + 1] = bReg[q].y;
                Bs[nxt][k][c + 2] = bReg[q].z;
                Bs[nxt][k][c + 3] = bReg[q].w;
            }
            __syncthreads();
        }
    }

#pragma unroll
    for (int mi = 0; mi < MT; mi++) {
        int r0 = rowBase + wm * WTM + mi * 16 + g;
        int r1 = r0 + 8;
        float s0 = (r0 < M) ? rs[r0] : 0.f;
        float s1 = (r1 < M) ? rs[r1] : 0.f;
#pragma unroll
        for (int ni = 0; ni < NT; ni++) {
            int c = wn * WTN + ni * 8 + tig * 2;
            if (r0 < M) {
                float2 o = make_float2(acc[mi][ni][0] * s0, acc[mi][ni][1] * s0);
                *reinterpret_cast<float2*>(C + (size_t)r0 * BN + c) = o;
            }
            if (r1 < M) {
                float2 o = make_float2(acc[mi][ni][2] * s1, acc[mi][ni][3] * s1);
                *reinterpret_cast<float2*>(C + (size_t)r1 * BN + c) = o;
            }
        }
    }
}

__global__ __launch_bounds__(256) void gemm1_kernel(const float* __restrict__ x,
                                                    const float* __restrict__ W1) {
    mma_gemm_core<F_HID, 2, 4>(x, W1, g_h1s, g_rs_out, NN, F_IN);
}

__global__ __launch_bounds__(256) void gemm2_kernel(const float* __restrict__ W2) {
    mma_gemm_core<F_OUT, 4, 2>(g_h1, W2, g_h2s, g_rs_out, NN, F_HID);
}

// ---------------- gather aggregation (CSR, warp per node) ----------------
__global__ void gather128_kernel(const float* __restrict__ b1) {
    int node = (blockIdx.x * blockDim.x + threadIdx.x) >> 5;
    int lane = threadIdx.x & 31;
    if (node >= NN) return;
    int start = g_row_start[node];
    int deg   = g_deg_in[node];
    float4 acc = make_float4(0.f, 0.f, 0.f, 0.f);
    for (int base = 0; base < deg; base += 32) {
        int e = base + lane;
        int sid = (e < deg) ? __ldg(&g_csr[start + e]) : 0;
        int cnt = min(32, deg - base);
        int j = 0;
        for (; j + 4 <= cnt; j += 4) {
            int s0 = __shfl_sync(0xFFFFFFFFu, sid, j);
            int s1 = __shfl_sync(0xFFFFFFFFu, sid, j + 1);
            int s2 = __shfl_sync(0xFFFFFFFFu, sid, j + 2);
            int s3 = __shfl_sync(0xFFFFFFFFu, sid, j + 3);
            float4 v0 = __ldg(reinterpret_cast<const float4*>(&g_h1s[(size_t)s0 * F_HID + lane * 4]));
            float4 v1 = __ldg(reinterpret_cast<const float4*>(&g_h1s[(size_t)s1 * F_HID + lane * 4]));
            float4 v2 = __ldg(reinterpret_cast<const float4*>(&g_h1s[(size_t)s2 * F_HID + lane * 4]));
            float4 v3 = __ldg(reinterpret_cast<const float4*>(&g_h1s[(size_t)s3 * F_HID + lane * 4]));
            acc.x += (v0.x + v1.x) + (v2.x + v3.x);
            acc.y += (v0.y + v1.y) + (v2.y + v3.y);
            acc.z += (v0.z + v1.z) + (v2.z + v3.z);
            acc.w += (v0.w + v1.w) + (v2.w + v3.w);
        }
        for (; j < cnt; j++) {
            int s = __shfl_sync(0xFFFFFFFFu, sid, j);
            float4 v = __ldg(reinterpret_cast<const float4*>(&g_h1s[(size_t)s * F_HID + lane * 4]));
            acc.x += v.x; acc.y += v.y; acc.z += v.z; acc.w += v.w;
        }
    }
    float rs = g_rs_in[node];
    float4 b = *reinterpret_cast<const float4*>(&b1[lane * 4]);
    float4 o;
    o.x = fmaxf(fmaf(acc.x, rs, b.x), 0.f);
    o.y = fmaxf(fmaf(acc.y, rs, b.y), 0.f);
    o.z = fmaxf(fmaf(acc.z, rs, b.z), 0.f);
    o.w = fmaxf(fmaf(acc.w, rs, b.w), 0.f);
    *reinterpret_cast<float4*>(&g_h1[(size_t)node * F_HID + lane * 4]) = o;
}

__global__ void gather64_kernel(const float* __restrict__ b2, const float* __restrict__ Wf,
                                const float* __restrict__ bf,
                                float* __restrict__ logits, float* __restrict__ hidden) {
    int node = (blockIdx.x * blockDim.x + threadIdx.x) >> 5;
    int lane = threadIdx.x & 31;
    if (node >= NN) return;
    int start = g_row_start[node];
    int deg   = g_deg_in[node];
    float2 acc = make_float2(0.f, 0.f);
    for (int base = 0; base < deg; base += 32) {
        int e = base + lane;
        int sid = (e < deg) ? __ldg(&g_csr[start + e]) : 0;
        int cnt = min(32, deg - base);
        int j = 0;
        for (; j + 4 <= cnt; j += 4) {
            int s0 = __shfl_sync(0xFFFFFFFFu, sid, j);
            int s1 = __shfl_sync(0xFFFFFFFFu, sid, j + 1);
            int s2 = __shfl_sync(0xFFFFFFFFu, sid, j + 2);
            int s3 = __shfl_sync(0xFFFFFFFFu, sid, j + 3);
            float2 v0 = __ldg(reinterpret_cast<const float2*>(&g_h2s[(size_t)s0 * F_OUT + lane * 2]));
            float2 v1 = __ldg(reinterpret_cast<const float2*>(&g_h2s[(size_t)s1 * F_OUT + lane * 2]));
            float2 v2 = __ldg(reinterpret_cast<const float2*>(&g_h2s[(size_t)s2 * F_OUT + lane * 2]));
            float2 v3 = __ldg(reinterpret_cast<const float2*>(&g_h2s[(size_t)s3 * F_OUT + lane * 2]));
            acc.x += (v0.x + v1.x) + (v2.x + v3.x);
            acc.y += (v0.y + v1.y) + (v2.y + v3.y);
        }
        for (; j < cnt; j++) {
            int s = __shfl_sync(0xFFFFFFFFu, sid, j);
            float2 v = __ldg(reinterpret_cast<const float2*>(&g_h2s[(size_t)s * F_OUT + lane * 2]));
            acc.x += v.x; acc.y += v.y;
        }
    }
    float rs = g_rs_in[node];
    float h0 = fmaf(acc.x, rs, b2[lane * 2]);
    float h1 = fmaf(acc.y, rs, b2[lane * 2 + 1]);
    *reinterpret_cast<float2*>(&hidden[(size_t)node * F_OUT + lane * 2]) = make_float2(h0, h1);

    float2 w0 = *reinterpret_cast<const float2*>(&Wf[(lane * 2) * 2]);
    float2 w1 = *reinterpret_cast<const float2*>(&Wf[(lane * 2 + 1) * 2]);
    float p0 = fmaf(h0, w0.x, h1 * w1.x);
    float p1 = fmaf(h0, w0.y, h1 * w1.y);
#pragma unroll
    for (int off = 16; off > 0; off >>= 1) {
        p0 += __shfl_down_sync(0xFFFFFFFFu, p0, off);
        p1 += __shfl_down_sync(0xFFFFFFFFu, p1, off);
    }
    if (lane == 0) {
        logits[(size_t)node * 2 + 0] = p0 + bf[0];
        logits[(size_t)node * 2 + 1] = p1 + bf[1];
    }
}

// ---------------- launcher ----------------
extern "C" void kernel_launch(void* const* d_in, const int* in_sizes, int n_in,
                              void* d_out, int out_size) {
    const float* x   = (const float*)d_in[0];
    const float* W1  = (const float*)d_in[1];
    const float* b1  = (const float*)d_in[2];
    const float* W2  = (const float*)d_in[3];
    const float* b2  = (const float*)d_in[4];
    const float* Wf  = (const float*)d_in[5];
    const float* bf  = (const float*)d_in[6];
    const int*   src = (const int*)d_in[7];
    const int*   dst = (const int*)d_in[8];

    float* out = (float*)d_out;
    float* logits = out;                       // [NN, 2]
    float* hidden = out + (size_t)NN * 2;      // [NN, 64]

    // serial prefix: zero + degree (everything depends on these)
    zero_counts_kernel<<<(NN + 255) / 256, 256>>>();
    degree_kernel<<<(NE + 255) / 256, 256>>>(src, dst);

    // ---- fork: CSR build on side stream, rsqrt+GEMM1 on main stream ----
    cudaEventRecord(g_fj.evFork, 0);
    cudaStreamWaitEvent(g_fj.s2, g_fj.evFork, 0);

    // side stream: CSR build (grouped by dst)
    scan_a_kernel<<<NBLK_SCAN, 256, 0, g_fj.s2>>>();
    scan_b_kernel<<<1, 256, 0, g_fj.s2>>>();
    scan_c_kernel<<<NBLK_SCAN, 256, 0, g_fj.s2>>>();
    bin_kernel<<<(NE + 255) / 256, 256, 0, g_fj.s2>>>(src, dst);
    cudaEventRecord(g_fj.evJoin, g_fj.s2);

    // main stream: norms + layer-1 transform
    rsqrt_kernel<<<(NN + 255) / 256, 256>>>();
    gemm1_kernel<<<(NN + 127) / 128, 256>>>(x, W1);

    // ---- join: gather needs CSR + h1s ----
    cudaStreamWaitEvent(0, g_fj.evJoin, 0);

    gather128_kernel<<<(NN * 32 + 255) / 256, 256>>>(b1);

    // Layer 2 + head
    gemm2_kernel<<<(NN + 127) / 128, 256>>>(W2);
    gather64_kernel<<<(NN * 32 + 255) / 256, 256>>>(b2, Wf, bf, logits, hidden);
}